// round 3
// baseline (speedup 1.0000x reference)
#include <cuda_runtime.h>
#include <cstddef>

// ---------------------------------------------------------------------------
// HMP hierarchical message passing — R3:
//  * f32x2 packed-FMA MLPs, 2 rows/thread, chunked 2nd layer (no reg spills)
//  * scatters fused into producer MLP epilogues (same idx arrays as gather)
//  * single upfront zero kernel for all accumulators
// ---------------------------------------------------------------------------

typedef unsigned long long ull;

#define N1MAX 250000
#define N2MAX 500000
#define N3MAX 1000000

// scratch (device globals: no allocation allowed)
__device__ float g_h2   [(size_t)N2MAX * 32];
__device__ float g_h3   [(size_t)N3MAX * 32];
__device__ float g_acc3 [(size_t)N3MAX * 32];
__device__ float g_acc2 [(size_t)N2MAX * 32];
__device__ float g_acc1 [(size_t)N1MAX * 32];
__device__ float g_accr [(size_t)N1MAX * 32];
__device__ float g_h1mid[(size_t)N1MAX * 32];

// ---------------------------------------------------------------------------
__device__ __forceinline__ ull pack2(float lo, float hi)
{
    ull p;
    asm("mov.b64 %0, {%1, %2};" : "=l"(p) : "f"(lo), "f"(hi));
    return p;
}
__device__ __forceinline__ void unpack2(ull p, float& lo, float& hi)
{
    asm("mov.b64 {%0, %1}, %2;" : "=f"(lo), "=f"(hi) : "l"(p));
}
// packed dual fp32 FMA (sm_100+)
__device__ __forceinline__ ull ffma2(ull a, ull b, ull c)
{
    ull d;
    asm("fma.rn.f32x2 %0, %1, %2, %3;" : "=l"(d) : "l"(a), "l"(b), "l"(c));
    return d;
}

__device__ __forceinline__ float tanh_fast(float x)
{
    float cx = fminf(fmaxf(x, -15.f), 15.f);
    float e  = __expf(2.f * cx);
    return __fdividef(e - 1.f, e + 1.f);
}

// ---------------------------------------------------------------------------
// zero 5 buffers in one kernel (grid-stride), counts in float4 units
__global__ void __launch_bounds__(256) zero_multi_kernel(
    float4* __restrict__ p0, int n0, float4* __restrict__ p1, int n1,
    float4* __restrict__ p2, int n2, float4* __restrict__ p3, int n3,
    float4* __restrict__ p4, int n4)
{
    const float4 z = make_float4(0.f, 0.f, 0.f, 0.f);
    int total = n0 + n1 + n2 + n3 + n4;
    for (int i = blockIdx.x * 256 + threadIdx.x; i < total; i += gridDim.x * 256) {
        int j = i;
        if (j < n0) { p0[j] = z; continue; } j -= n0;
        if (j < n1) { p1[j] = z; continue; } j -= n1;
        if (j < n2) { p2[j] = z; continue; } j -= n2;
        if (j < n3) { p3[j] = z; continue; } j -= n3;
        p4[j] = z;
    }
}

// ---------------------------------------------------------------------------
// Generic 2-rows/thread MLP:
//   x = [ self[r] | block1 | (block2) ]  (P=2 or 3 input blocks of 32)
//   GATHER: block1 = other[gi0[r]], block2 = other[gi1[r]]
//   else  : block1 = other[r] (P must be 2)
//   out[r] = tanh(x@W1+b1)@W2+b2
//   SCATTER: atomically add out row into acc[si0[r]] and acc[si1[r]]
template<int P, bool GATHER, bool SCATTER>
__global__ void __launch_bounds__(128) mlp2_kernel(
    const float* __restrict__ self, const float* __restrict__ other,
    const int* __restrict__ gi0, const int* __restrict__ gi1,
    const float* __restrict__ W1, const float* __restrict__ b1,
    const float* __restrict__ W2, const float* __restrict__ b2,
    float* __restrict__ out,
    float* __restrict__ acc,
    const int* __restrict__ si0, const int* __restrict__ si1,
    int n)
{
    __shared__ __align__(16) ull sW1[P * 32 * 32];   // duplicated (w,w) pairs
    __shared__ __align__(16) ull sW2[32 * 32];
    __shared__ ull sB1[32], sB2[32];
    for (int t = threadIdx.x; t < P * 32 * 32; t += 128) { float w = W1[t]; sW1[t] = pack2(w, w); }
    for (int t = threadIdx.x; t < 32 * 32; t += 128)     { float w = W2[t]; sW2[t] = pack2(w, w); }
    if (threadIdx.x < 32) {
        float v = b1[threadIdx.x]; sB1[threadIdx.x] = pack2(v, v);
        float u = b2[threadIdx.x]; sB2[threadIdx.x] = pack2(u, u);
    }
    __syncthreads();

    int t  = blockIdx.x * 128 + threadIdx.x;
    int r0 = 2 * t;
    if (r0 >= n) return;
    int r1 = min(r0 + 1, n - 1);
    bool two = (r1 != r0);

    const float4* a0[P];
    const float4* a1[P];
    a0[0] = (const float4*)(self + (size_t)r0 * 32);
    a1[0] = (const float4*)(self + (size_t)r1 * 32);
    if (GATHER) {
        a0[1] = (const float4*)(other + (size_t)gi0[r0] * 32);
        a1[1] = (const float4*)(other + (size_t)gi0[r1] * 32);
        if (P == 3) {
            a0[2] = (const float4*)(other + (size_t)gi1[r0] * 32);
            a1[2] = (const float4*)(other + (size_t)gi1[r1] * 32);
        }
    } else {
        a0[1] = (const float4*)(other + (size_t)r0 * 32);
        a1[1] = (const float4*)(other + (size_t)r1 * 32);
    }

    // ---------------- layer 1: [2 x P*32] @ [P*32 x 32] ----------------
    ull acch[32];
#pragma unroll
    for (int j = 0; j < 32; j++) acch[j] = sB1[j];

#pragma unroll
    for (int p = 0; p < P; p++) {
#pragma unroll 2
        for (int k4 = 0; k4 < 8; k4++) {
            float4 v0 = a0[p][k4];
            float4 v1 = a1[p][k4];
            ull xp[4];
            xp[0] = pack2(v0.x, v1.x); xp[1] = pack2(v0.y, v1.y);
            xp[2] = pack2(v0.z, v1.z); xp[3] = pack2(v0.w, v1.w);
#pragma unroll
            for (int kk = 0; kk < 4; kk++) {
                const ulonglong2* wrow =
                    (const ulonglong2*)(sW1 + ((p * 8 + k4) * 4 + kk) * 32);
#pragma unroll
                for (int j2 = 0; j2 < 16; j2++) {
                    ulonglong2 w = wrow[j2];
                    acch[2 * j2]     = ffma2(xp[kk], w.x, acch[2 * j2]);
                    acch[2 * j2 + 1] = ffma2(xp[kk], w.y, acch[2 * j2 + 1]);
                }
            }
        }
    }

#pragma unroll
    for (int j = 0; j < 32; j++) {
        float u, v; unpack2(acch[j], u, v);
        acch[j] = pack2(tanh_fast(u), tanh_fast(v));
    }

    // ---------------- layer 2, chunked: 8 output neurons at a time ------
    float4* o0base = (float4*)(out + (size_t)r0 * 32);
    float4* o1base = (float4*)(out + (size_t)r1 * 32);
    float4* d00 = 0; float4* d01 = 0; float4* d10 = 0; float4* d11 = 0;
    if (SCATTER) {
        d00 = (float4*)(acc + (size_t)si0[r0] * 32);
        d01 = (float4*)(acc + (size_t)si1[r0] * 32);
        d10 = (float4*)(acc + (size_t)si0[r1] * 32);
        d11 = (float4*)(acc + (size_t)si1[r1] * 32);
    }

#pragma unroll
    for (int jc = 0; jc < 4; jc++) {
        ull o8[8];
#pragma unroll
        for (int m = 0; m < 8; m++) o8[m] = sB2[jc * 8 + m];
#pragma unroll 4
        for (int k = 0; k < 32; k++) {
            const ulonglong2* wrow = (const ulonglong2*)(sW2 + k * 32 + jc * 8);
            ull hk = acch[k];
#pragma unroll
            for (int m2 = 0; m2 < 4; m2++) {
                ulonglong2 w = wrow[m2];
                o8[2 * m2]     = ffma2(hk, w.x, o8[2 * m2]);
                o8[2 * m2 + 1] = ffma2(hk, w.y, o8[2 * m2 + 1]);
            }
        }
        float r0v[8], r1v[8];
#pragma unroll
        for (int m = 0; m < 8; m++) unpack2(o8[m], r0v[m], r1v[m]);

        float4 f00 = make_float4(r0v[0], r0v[1], r0v[2], r0v[3]);
        float4 f01 = make_float4(r0v[4], r0v[5], r0v[6], r0v[7]);
        float4 f10 = make_float4(r1v[0], r1v[1], r1v[2], r1v[3]);
        float4 f11 = make_float4(r1v[4], r1v[5], r1v[6], r1v[7]);

        o0base[jc * 2]     = f00;
        o0base[jc * 2 + 1] = f01;
        if (two) {
            o1base[jc * 2]     = f10;
            o1base[jc * 2 + 1] = f11;
        }
        if (SCATTER) {
            atomicAdd(d00 + jc * 2,     f00);
            atomicAdd(d00 + jc * 2 + 1, f01);
            atomicAdd(d01 + jc * 2,     f00);
            atomicAdd(d01 + jc * 2 + 1, f01);
            if (two) {
                atomicAdd(d10 + jc * 2,     f10);
                atomicAdd(d10 + jc * 2 + 1, f11);
                atomicAdd(d11 + jc * 2,     f10);
                atomicAdd(d11 + jc * 2 + 1, f11);
            }
        }
    }
}

// ---------------------------------------------------------------------------
// acc[dstidx[r]] += src[srcidx[r]]  (ring edges)
__global__ void __launch_bounds__(256) scatter1_kernel(
    const float* __restrict__ src,
    const int* __restrict__ srcidx, const int* __restrict__ dstidx,
    float* __restrict__ acc, int n)
{
    int r = blockIdx.x * 256 + threadIdx.x;
    if (r >= n) return;
    const float4* s = (const float4*)(src + (size_t)srcidx[r] * 32);
    float4* d = (float4*)(acc + (size_t)dstidx[r] * 32);
#pragma unroll
    for (int q = 0; q < 8; q++) atomicAdd(d + q, s[q]);
}

// ---------------------------------------------------------------------------
static inline int nblk256(int n) { return (n + 255) / 256; }
static inline int nblk2(int n)   { return (n + 255) / 256; }  // 128 thr x 2 rows

extern "C" void kernel_launch(void* const* d_in, const int* in_sizes, int n_in,
                              void* d_out, int out_size)
{
    const float* h1     = (const float*)d_in[0];
    const float* h2     = (const float*)d_in[1];
    const float* h3     = (const float*)d_in[2];
    const float* h4     = (const float*)d_in[3];
    const float* upW1   = (const float*)d_in[4];
    const float* upb1   = (const float*)d_in[5];
    const float* upW2   = (const float*)d_in[6];
    const float* upb2   = (const float*)d_in[7];
    const float* dnW1   = (const float*)d_in[8];
    const float* dnb1   = (const float*)d_in[9];
    const float* dnW2   = (const float*)d_in[10];
    const float* dnb2   = (const float*)d_in[11];
    const float* rW1    = (const float*)d_in[12];
    const float* rb1    = (const float*)d_in[13];
    const float* rW2    = (const float*)d_in[14];
    const float* rb2    = (const float*)d_in[15];
    const int* idx2_0   = (const int*)d_in[16];
    const int* idx2_1   = (const int*)d_in[17];
    const int* idx3_0   = (const int*)d_in[18];
    const int* idx3_1   = (const int*)d_in[19];
    const int* idx4_0   = (const int*)d_in[20];
    const int* idx4_1   = (const int*)d_in[21];
    const int* ring_src = (const int*)d_in[22];
    const int* ring_dst = (const int*)d_in[23];

    const int N1 = in_sizes[0] / 32;
    const int N2 = in_sizes[1] / 32;
    const int N3 = in_sizes[2] / 32;
    const int N4 = in_sizes[3] / 32;
    const int ER = in_sizes[22];
    const int NR = out_size / 32 - (N1 + N2 + N3 + N4);

    float* out  = (float*)d_out;
    float* out1 = out;
    float* out2 = out1 + (size_t)N1 * 32;
    float* out3 = out2 + (size_t)N2 * 32;
    float* out4 = out3 + (size_t)N3 * 32;
    float* outR = out4 + (size_t)N4 * 32;

    float *h2buf, *h3buf, *acc3, *acc2, *acc1, *accr, *h1mid;
    cudaGetSymbolAddress((void**)&h2buf, g_h2);
    cudaGetSymbolAddress((void**)&h3buf, g_h3);
    cudaGetSymbolAddress((void**)&acc3,  g_acc3);
    cudaGetSymbolAddress((void**)&acc2,  g_acc2);
    cudaGetSymbolAddress((void**)&acc1,  g_acc1);
    cudaGetSymbolAddress((void**)&accr,  g_accr);
    cudaGetSymbolAddress((void**)&h1mid, g_h1mid);

    // ---- 0: zero all accumulators in one kernel ----
    zero_multi_kernel<<<2048, 256>>>(
        (float4*)acc3, N3 * 8, (float4*)acc2, N2 * 8,
        (float4*)acc1, N1 * 8, (float4*)accr, N1 * 8,
        (float4*)outR, NR * 8);

    // ---- up pass ----
    mlp2_kernel<3, true, false><<<nblk2(N2), 128>>>(h2, h1, idx2_0, idx2_1,
        upW1 + 0 * 96 * 32, upb1 + 0 * 32, upW2 + 0 * 1024, upb2 + 0 * 32,
        h2buf, 0, 0, 0, N2);
    mlp2_kernel<3, true, false><<<nblk2(N3), 128>>>(h3, h2buf, idx3_0, idx3_1,
        upW1 + 1 * 96 * 32, upb1 + 1 * 32, upW2 + 1 * 1024, upb2 + 1 * 32,
        h3buf, 0, 0, 0, N3);
    // up4: fused scatter into acc3 (same idx arrays)
    mlp2_kernel<3, true, true><<<nblk2(N4), 128>>>(h4, h3buf, idx4_0, idx4_1,
        upW1 + 2 * 96 * 32, upb1 + 2 * 32, upW2 + 2 * 1024, upb2 + 2 * 32,
        out4, acc3, idx4_0, idx4_1, N4);

    // ---- down pass (scatter fused into epilogues) ----
    mlp2_kernel<2, false, true><<<nblk2(N3), 128>>>(h3buf, acc3, 0, 0,
        dnW1 + 2 * 64 * 32, dnb1 + 2 * 32, dnW2 + 2 * 1024, dnb2 + 2 * 32,
        out3, acc2, idx3_0, idx3_1, N3);
    mlp2_kernel<2, false, true><<<nblk2(N2), 128>>>(h2buf, acc2, 0, 0,
        dnW1 + 1 * 64 * 32, dnb1 + 1 * 32, dnW2 + 1 * 1024, dnb2 + 1 * 32,
        out2, acc1, idx2_0, idx2_1, N2);
    mlp2_kernel<2, false, false><<<nblk2(N1), 128>>>(h1, acc1, 0, 0,
        dnW1 + 0 * 64 * 32, dnb1 + 0 * 32, dnW2 + 0 * 1024, dnb2 + 0 * 32,
        h1mid, 0, 0, 0, N1);

    // ---- ring ----
    scatter1_kernel<<<nblk256(ER), 256>>>(h1mid, ring_src, ring_dst, outR, ER);
    scatter1_kernel<<<nblk256(ER), 256>>>(outR, ring_dst, ring_src, accr, ER);
    mlp2_kernel<2, false, false><<<nblk2(N1), 128>>>(h1mid, accr, 0, 0,
        rW1, rb1, rW2, rb2, out1, 0, 0, 0, N1);
}